// round 6
// baseline (speedup 1.0000x reference)
#include <cuda_runtime.h>
#include <math.h>
#include <stdint.h>

// MemoryUnit, Round 5: 2-CTA cluster per batch element.
// Algebraic reduction: k,v slot-GEMMs replaced by
//   logits = M @ (Wk q) + q.bk      (q computed first, exchanged)
//   r      = (attn @ M) @ Wv + bv
// All 256 threads homogeneous: op = tid>>2 (64 o-pairs), ih = tid&3 (i quarter).
// Batched register loads for high MLP in all weight loops.

namespace {
constexpr int S_ = 2048;
constexpr int B_ = 64;
constexpr int D_ = 256;
constexpr int K_ = 16;
constexpr int NT = 256;
constexpr float EPSLN = 1e-5f;
constexpr float MOMC  = 0.9f;

__device__ __forceinline__ float geluf(float v) {
    return 0.5f * v * (1.0f + erff(v * 0.70710678118654752440f));
}
__device__ __forceinline__ float sigmf(float v) {
    return 1.0f / (1.0f + expf(-v));
}
__device__ __forceinline__ uint32_t smem_u32(const void* p) {
    return (uint32_t)__cvta_generic_to_shared(const_cast<void*>(p));
}
__device__ __forceinline__ uint32_t peer_addr(uint32_t la, uint32_t peer) {
    uint32_t ra;
    asm("mapa.shared::cluster.u32 %0, %1, %2;" : "=r"(ra) : "r"(la), "r"(peer));
    return ra;
}
__device__ __forceinline__ void st_peer_f32(uint32_t ra, float v) {
    asm volatile("st.shared::cluster.f32 [%0], %1;" :: "r"(ra), "f"(v) : "memory");
}
__device__ __forceinline__ void st_peer_f64(uint32_t ra, float a, float b) {
    asm volatile("st.shared::cluster.v2.f32 [%0], {%1,%2};"
                 :: "r"(ra), "f"(a), "f"(b) : "memory");
}
__device__ __forceinline__ void st_peer_f128(uint32_t ra, float4 v) {
    asm volatile("st.shared::cluster.v4.f32 [%0], {%1,%2,%3,%4};"
                 :: "r"(ra), "f"(v.x), "f"(v.y), "f"(v.z), "f"(v.w) : "memory");
}
__device__ __forceinline__ void cluster_sync_() {
    asm volatile("barrier.cluster.arrive.aligned;\n\t"
                 "barrier.cluster.wait.aligned;" ::: "memory");
}
__device__ __forceinline__ float2 ld2(const float* p) {
    return *reinterpret_cast<const float2*>(p);
}
__device__ __forceinline__ float red4(float v) {
    v += __shfl_xor_sync(0xffffffffu, v, 1);
    v += __shfl_xor_sync(0xffffffffu, v, 2);
    return v;
}
} // namespace

__global__ __launch_bounds__(NT, 1) __cluster_dims__(2, 1, 1)
void memunit_kernel(
    const float* __restrict__ x,     const float* __restrict__ slot_init,
    const float* __restrict__ Wq,    const float* __restrict__ bq,
    const float* __restrict__ Wk,    const float* __restrict__ bk,
    const float* __restrict__ Wv,    const float* __restrict__ bv,
    const float* __restrict__ wg1W,  const float* __restrict__ wg1b,
    const float* __restrict__ wg2W,  const float* __restrict__ wg2b,
    const float* __restrict__ egW,   const float* __restrict__ egb,
    const float* __restrict__ wcW,   const float* __restrict__ wcb,
    const float* __restrict__ wclng, const float* __restrict__ wclnb,
    const float* __restrict__ fuW,   const float* __restrict__ fub,
    const float* __restrict__ fulng, const float* __restrict__ fulnb,
    const float* __restrict__ ong,   const float* __restrict__ onb,
    float* __restrict__ out)
{
    __shared__ float sM[D_][K_];       // full M, feature-major, mirrored via DSMEM
    __shared__ float scat[2 * D_];     // [x_t | r]
    __shared__ float sQ[D_];           // full q (with bias), both halves
    __shared__ float sKv[128];         // Kvec for my CTA's 128 rows
    __shared__ float sMbar[D_];        // attn-weighted slot average
    __shared__ float sQB[8];           // q.bk warp partials
    __shared__ float sLP[4][K_];       // logit warp partials
    __shared__ float sGP[8][2 * K_];   // gstat warp partials
    __shared__ float sGloc[2 * K_], eG[2 * K_];
    __shared__ float sLoc[17], eL[17]; // logits + qdotbk halves
    __shared__ float sBR[8][3];
    __shared__ float sF[3], eF[3], sU[2], eU[2];
    __shared__ float sAttn[K_], sEvict[K_], sPers[K_], sMean[K_], sRstd[K_];
    __shared__ float sNov;

    const int tid  = threadIdx.x;
    const int lane = tid & 31;
    const int wid  = tid >> 5;
    const int ih   = tid & 3;          // i-quarter
    const int op   = tid >> 2;         // o-pair 0..63
    uint32_t rank;
    asm("mov.u32 %0, %%cluster_ctarank;" : "=r"(rank));
    const uint32_t peer = rank ^ 1u;
    const int b  = blockIdx.x >> 1;
    const int og = (int)rank * 128 + op * 2;

    #pragma unroll
    for (int j = 0; j < K_; ++j) sM[tid][j] = slot_init[j * D_ + tid];
    if (tid < K_) sPers[tid] = 0.f;

    const float2 bqv = ld2(bq + og), bkv = ld2(bk + og), bvv = ld2(bv + og);
    const float2 egbv = ld2(egb + og), wcbv = ld2(wcb + og);
    const float2 wclngv = ld2(wclng + og), wclnbv = ld2(wclnb + og);
    const float2 fubv = ld2(fub + og), fulngv = ld2(fulng + og), fulnbv = ld2(fulnb + og);
    const float2 wg1bv = ld2(wg1b + og), wg2wv = ld2(wg2W + og);
    const float  wg2b0 = wg2b[0];
    const float2 ongv = ld2(ong + og), onbv = ld2(onb + og);

    for (int t = 0; t < S_; ++t) {
        scat[tid] = x[((size_t)t * B_ + b) * D_ + tid];
        __syncthreads();

        const int i0 = ih * 64;

        // ---- q = x @ Wq + bq (my o-half, i-quarter) ----
        float q0 = 0.f, q1 = 0.f;
        for (int c = 0; c < 64; c += 16) {
            float2 w[16];
            #pragma unroll
            for (int u = 0; u < 16; ++u) w[u] = ld2(Wq + (i0 + c + u) * D_ + og);
            #pragma unroll
            for (int u = 0; u < 16; ++u) {
                const float xv = scat[i0 + c + u];
                q0 = fmaf(xv, w[u].x, q0);
                q1 = fmaf(xv, w[u].y, q1);
            }
        }
        q0 = red4(q0) + bqv.x;
        q1 = red4(q1) + bqv.y;
        if (ih == 0)      { sQ[og] = q0; sQ[og + 1] = q1; }
        else if (ih == 1) st_peer_f64(peer_addr(smem_u32(&sQ[og]), peer), q0, q1);
        // q . bk partial (each o once via ih==0)
        {
            float v = (ih == 0) ? q0 * bkv.x + q1 * bkv.y : 0.f;
            #pragma unroll
            for (int off = 1; off < 32; off <<= 1)
                v += __shfl_xor_sync(0xffffffffu, v, off);
            if (lane == 0) sQB[wid] = v;
        }

        // ---- big eg/wc GEMM (slot parts + x-halves) ----
        float ae0[K_], ae1[K_], aw0[K_], aw1[K_];
        float ce0 = 0.f, ce1 = 0.f, cw0 = 0.f, cw1 = 0.f;
        #pragma unroll
        for (int j = 0; j < K_; ++j) { ae0[j]=0.f; ae1[j]=0.f; aw0[j]=0.f; aw1[j]=0.f; }
        for (int c = 0; c < 64; c += 8) {
            float2 vEL[8], vEH[8], vWL[8], vWH[8];
            #pragma unroll
            for (int u = 0; u < 8; ++u) {
                const int lo = (i0 + c + u) * D_ + og;
                vEL[u] = ld2(egW + lo); vEH[u] = ld2(egW + lo + D_ * D_);
                vWL[u] = ld2(wcW + lo); vWH[u] = ld2(wcW + lo + D_ * D_);
            }
            #pragma unroll
            for (int u = 0; u < 8; ++u) {
                const int i = i0 + c + u;
                const float xv = scat[i];
                const float4* mr = reinterpret_cast<const float4*>(sM[i]);
                const float4 m0 = mr[0], m1 = mr[1], m2 = mr[2], m3 = mr[3];
                ce0 = fmaf(xv, vEL[u].x, ce0); ce1 = fmaf(xv, vEL[u].y, ce1);
                cw0 = fmaf(xv, vWL[u].x, cw0); cw1 = fmaf(xv, vWL[u].y, cw1);
                const float mv[K_] = {m0.x,m0.y,m0.z,m0.w, m1.x,m1.y,m1.z,m1.w,
                                      m2.x,m2.y,m2.z,m2.w, m3.x,m3.y,m3.z,m3.w};
                #pragma unroll
                for (int j = 0; j < K_; ++j) {
                    ae0[j] = fmaf(mv[j], vEH[u].x, ae0[j]);
                    ae1[j] = fmaf(mv[j], vEH[u].y, ae1[j]);
                    aw0[j] = fmaf(mv[j], vWH[u].x, aw0[j]);
                    aw1[j] = fmaf(mv[j], vWH[u].y, aw1[j]);
                }
            }
        }
        ce0 = red4(ce0); ce1 = red4(ce1); cw0 = red4(cw0); cw1 = red4(cw1);
        #pragma unroll
        for (int j = 0; j < K_; ++j) {
            ae0[j] = red4(ae0[j]); ae1[j] = red4(ae1[j]);
            aw0[j] = red4(aw0[j]); aw1[j] = red4(aw1[j]);
        }
        // write candidate gelu + LN partials
        float g0[K_], g1[K_];
        {
            float gs[K_], gq[K_];
            #pragma unroll
            for (int j = 0; j < K_; ++j) {
                g0[j] = geluf(aw0[j] + cw0 + wcbv.x);
                g1[j] = geluf(aw1[j] + cw1 + wcbv.y);
                gs[j] = g0[j] + g1[j];
                gq[j] = g0[j] * g0[j] + g1[j] * g1[j];
            }
            #pragma unroll
            for (int off = 4; off <= 16; off <<= 1) {
                #pragma unroll
                for (int j = 0; j < K_; ++j) {
                    gs[j] += __shfl_xor_sync(0xffffffffu, gs[j], off);
                    gq[j] += __shfl_xor_sync(0xffffffffu, gq[j], off);
                }
            }
            if (lane == 0) {
                #pragma unroll
                for (int j = 0; j < K_; ++j) {
                    sGP[wid][j] = gs[j];
                    sGP[wid][K_ + j] = gq[j];
                }
            }
        }
        cluster_sync_();   // B0: full q visible in both CTAs

        // ---- Kvec_i = sum_o Wk[i,o] q_o for my 128 rows ----
        {
            const int e  = tid >> 1;
            const int oh = tid & 1;
            const float4* wr = reinterpret_cast<const float4*>(
                Wk + (size_t)((int)rank * 128 + e) * D_ + oh * 128);
            const float4* qv = reinterpret_cast<const float4*>(sQ + oh * 128);
            float acc = 0.f;
            #pragma unroll
            for (int u = 0; u < 32; ++u) {
                const float4 w4 = wr[u];
                const float4 q4 = qv[u];
                acc = fmaf(w4.x, q4.x, acc);
                acc = fmaf(w4.y, q4.y, acc);
                acc = fmaf(w4.z, q4.z, acc);
                acc = fmaf(w4.w, q4.w, acc);
            }
            acc += __shfl_xor_sync(0xffffffffu, acc, 1);
            if (oh == 0) sKv[e] = acc;
        }
        __syncthreads();

        // ---- logit partials over my 128 rows ----
        if (tid < 128) {
            const int gi = (int)rank * 128 + tid;
            const float kv = sKv[tid];
            const float4* mr = reinterpret_cast<const float4*>(sM[gi]);
            const float4 m0 = mr[0], m1 = mr[1], m2 = mr[2], m3 = mr[3];
            const float mv[K_] = {m0.x,m0.y,m0.z,m0.w, m1.x,m1.y,m1.z,m1.w,
                                  m2.x,m2.y,m2.z,m2.w, m3.x,m3.y,m3.z,m3.w};
            float p[K_];
            #pragma unroll
            for (int j = 0; j < K_; ++j) p[j] = mv[j] * kv;
            #pragma unroll
            for (int off = 1; off < 32; off <<= 1) {
                #pragma unroll
                for (int j = 0; j < K_; ++j)
                    p[j] += __shfl_xor_sync(0xffffffffu, p[j], off);
            }
            if (lane == 0) {
                #pragma unroll
                for (int j = 0; j < K_; ++j) sLP[wid][j] = p[j];
            }
        }
        __syncthreads();
        if (tid < K_) {
            const float s = sLP[0][tid] + sLP[1][tid] + sLP[2][tid] + sLP[3][tid];
            sLoc[tid] = s;
            st_peer_f32(peer_addr(smem_u32(&eL[tid]), peer), s);
        } else if (tid == K_) {
            float s = 0.f;
            #pragma unroll
            for (int w = 0; w < 8; ++w) s += sQB[w];
            sLoc[K_] = s;
            st_peer_f32(peer_addr(smem_u32(&eL[K_]), peer), s);
        }
        cluster_sync_();   // B1: logit halves + qdotbk exchanged

        if (tid < K_) {
            const float qb = sLoc[K_] + eL[K_];
            float l = (sLoc[tid] + eL[tid] + qb) * 0.0625f;
            float mx = l;
            #pragma unroll
            for (int off = 8; off; off >>= 1) mx = fmaxf(mx, __shfl_xor_sync(0xffffu, mx, off, 16));
            const float e = expf(l - mx);
            float s = e;
            #pragma unroll
            for (int off = 8; off; off >>= 1) s += __shfl_xor_sync(0xffffu, s, off, 16);
            const float a = e / s;
            sAttn[tid] = a;
            if (tid == 0) sNov = 1.f - 1.f / s;
            const float pr = MOMC * sPers[tid] + (1.f - MOMC) * a;
            sPers[tid] = pr;
            float el = -4.f * pr, em = el;
            #pragma unroll
            for (int off = 8; off; off >>= 1) em = fmaxf(em, __shfl_xor_sync(0xffffu, em, off, 16));
            const float ee = expf(el - em);
            float es = ee;
            #pragma unroll
            for (int off = 8; off; off >>= 1) es += __shfl_xor_sync(0xffffu, es, off, 16);
            sEvict[tid] = ee / es;
        }
        __syncthreads();

        // ---- m-bar = attn @ M (full, local) ----
        {
            const float4* mr = reinterpret_cast<const float4*>(sM[tid]);
            const float4 m0 = mr[0], m1 = mr[1], m2 = mr[2], m3 = mr[3];
            const float mv[K_] = {m0.x,m0.y,m0.z,m0.w, m1.x,m1.y,m1.z,m1.w,
                                  m2.x,m2.y,m2.z,m2.w, m3.x,m3.y,m3.z,m3.w};
            float acc = 0.f;
            #pragma unroll
            for (int j = 0; j < K_; ++j) acc = fmaf(sAttn[j], mv[j], acc);
            sMbar[tid] = acc;
        }
        __syncthreads();

        // ---- r = m-bar @ Wv + bv ----
        float r0 = 0.f, r1 = 0.f;
        for (int c = 0; c < 64; c += 16) {
            float2 w[16];
            #pragma unroll
            for (int u = 0; u < 16; ++u) w[u] = ld2(Wv + (i0 + c + u) * D_ + og);
            #pragma unroll
            for (int u = 0; u < 16; ++u) {
                const float mb = sMbar[i0 + c + u];
                r0 = fmaf(mb, w[u].x, r0);
                r1 = fmaf(mb, w[u].y, r1);
            }
        }
        r0 = red4(r0) + bvv.x;
        r1 = red4(r1) + bvv.y;
        if (ih == 0)      { scat[D_ + og] = r0; scat[D_ + og + 1] = r1; }
        else if (ih == 1) st_peer_f64(peer_addr(smem_u32(&scat[D_ + og]), peer), r0, r1);
        // gstat combine + exchange
        if (tid < 2 * K_) {
            float s = 0.f;
            #pragma unroll
            for (int w = 0; w < 8; ++w) s += sGP[w][tid];
            sGloc[tid] = s;
            st_peer_f32(peer_addr(smem_u32(&eG[tid]), peer), s);
        }
        cluster_sync_();   // B2: cat complete + gstats exchanged

        if (tid < K_) {
            const float gsum = sGloc[tid] + eG[tid];
            const float gsq  = sGloc[K_ + tid] + eG[K_ + tid];
            const float mean = gsum * (1.f / D_);
            const float var  = gsq * (1.f / D_) - mean * mean;
            sMean[tid] = mean;
            sRstd[tid] = rsqrtf(var + EPSLN);
        }
        __syncthreads();

        // ---- fu / wg1 over cat (i-quarter of 512) ----
        float af0 = 0.f, af1 = 0.f, ag0 = 0.f, ag1 = 0.f;
        const int c0 = ih * 128;
        for (int c = 0; c < 128; c += 8) {
            float2 vF[8], vG[8];
            #pragma unroll
            for (int u = 0; u < 8; ++u) {
                const int wix = (c0 + c + u) * D_ + og;
                vF[u] = ld2(fuW + wix);
                vG[u] = ld2(wg1W + wix);
            }
            #pragma unroll
            for (int u = 0; u < 8; ++u) {
                const float cv = scat[c0 + c + u];
                af0 = fmaf(cv, vF[u].x, af0); af1 = fmaf(cv, vF[u].y, af1);
                ag0 = fmaf(cv, vG[u].x, ag0); ag1 = fmaf(cv, vG[u].y, ag1);
            }
        }
        af0 = red4(af0); af1 = red4(af1);
        ag0 = red4(ag0); ag1 = red4(ag1);
        const float hf0 = geluf(af0 + fubv.x);
        const float hf1 = geluf(af1 + fubv.y);
        const float hg0 = geluf(ag0 + wg1bv.x);
        const float hg1 = geluf(ag1 + wg1bv.y);
        {
            float a0 = hf0 + hf1;
            float a1 = hf0 * hf0 + hf1 * hf1;
            float a2 = hg0 * wg2wv.x + hg1 * wg2wv.y;
            #pragma unroll
            for (int off = 4; off <= 16; off <<= 1) {
                a0 += __shfl_xor_sync(0xffffffffu, a0, off);
                a1 += __shfl_xor_sync(0xffffffffu, a1, off);
                a2 += __shfl_xor_sync(0xffffffffu, a2, off);
            }
            if (lane == 0) { sBR[wid][0] = a0; sBR[wid][1] = a1; sBR[wid][2] = a2; }
        }
        __syncthreads();
        if (tid < 3) {
            float s = 0.f;
            #pragma unroll
            for (int w = 0; w < 8; ++w) s += sBR[w][tid];
            sF[tid] = s;
            st_peer_f32(peer_addr(smem_u32(&eF[tid]), peer), s);
        }
        cluster_sync_();   // B3: fu-LN + wg2 partials exchanged

        const float fsum = sF[0] + eF[0], fsq = sF[1] + eF[1], wgs = sF[2] + eF[2];
        const float fmn = fsum * (1.f / D_);
        const float fvr = fsq * (1.f / D_) - fmn * fmn;
        const float frs = rsqrtf(fvr + EPSLN);
        const float outt0 = (hf0 - fmn) * frs * fulngv.x + fulnbv.x;
        const float outt1 = (hf1 - fmn) * frs * fulngv.y + fulnbv.y;
        const float gw = sigmf(wgs + wg2b0) * sNov;
        if (tid < K_) sPers[tid] += sEvict[tid] * gw * 0.1f;

        const float u0 = outt0 + scat[og];
        const float u1 = outt1 + scat[og + 1];
        {
            float b0 = u0 + u1;
            float b1 = u0 * u0 + u1 * u1;
            #pragma unroll
            for (int off = 4; off <= 16; off <<= 1) {
                b0 += __shfl_xor_sync(0xffffffffu, b0, off);
                b1 += __shfl_xor_sync(0xffffffffu, b1, off);
            }
            if (lane == 0) { sBR[wid][0] = b0; sBR[wid][1] = b1; }
        }
        __syncthreads();
        if (tid < 2) {
            float s = 0.f;
            #pragma unroll
            for (int w = 0; w < 8; ++w) s += sBR[w][tid];
            sU[tid] = s;
            st_peer_f32(peer_addr(smem_u32(&eU[tid]), peer), s);
        }

        // ---- memory update (all ih hold identical reduced values) ----
        {
            float nmA[K_], nmB[K_];
            #pragma unroll
            for (int j = 0; j < K_; ++j) {
                const float er0 = sigmf(ae0[j] + ce0 + egbv.x);
                const float er1 = sigmf(ae1[j] + ce1 + egbv.y);
                const float wr0 = (g0[j] - sMean[j]) * sRstd[j] * wclngv.x + wclnbv.x;
                const float wr1 = (g1[j] - sMean[j]) * sRstd[j] * wclngv.y + wclnbv.y;
                const float al = gw * sEvict[j];
                nmA[j] = sM[og][j]     * (1.f - al * er0) + al * wr0;
                nmB[j] = sM[og + 1][j] * (1.f - al * er1) + al * wr1;
            }
            if (ih == 0) {
                float4* rA = reinterpret_cast<float4*>(sM[og]);
                float4* rB = reinterpret_cast<float4*>(sM[og + 1]);
                rA[0] = make_float4(nmA[0], nmA[1], nmA[2], nmA[3]);
                rA[1] = make_float4(nmA[4], nmA[5], nmA[6], nmA[7]);
                rA[2] = make_float4(nmA[8], nmA[9], nmA[10], nmA[11]);
                rA[3] = make_float4(nmA[12], nmA[13], nmA[14], nmA[15]);
                rB[0] = make_float4(nmB[0], nmB[1], nmB[2], nmB[3]);
                rB[1] = make_float4(nmB[4], nmB[5], nmB[6], nmB[7]);
                rB[2] = make_float4(nmB[8], nmB[9], nmB[10], nmB[11]);
                rB[3] = make_float4(nmB[12], nmB[13], nmB[14], nmB[15]);
            } else if (ih == 1) {
                uint32_t ra = peer_addr(smem_u32(&sM[og][0]), peer);
                st_peer_f128(ra,      make_float4(nmA[0], nmA[1], nmA[2], nmA[3]));
                st_peer_f128(ra + 16, make_float4(nmA[4], nmA[5], nmA[6], nmA[7]));
                st_peer_f128(ra + 32, make_float4(nmA[8], nmA[9], nmA[10], nmA[11]));
                st_peer_f128(ra + 48, make_float4(nmA[12], nmA[13], nmA[14], nmA[15]));
                uint32_t rb = peer_addr(smem_u32(&sM[og + 1][0]), peer);
                st_peer_f128(rb,      make_float4(nmB[0], nmB[1], nmB[2], nmB[3]));
                st_peer_f128(rb + 16, make_float4(nmB[4], nmB[5], nmB[6], nmB[7]));
                st_peer_f128(rb + 32, make_float4(nmB[8], nmB[9], nmB[10], nmB[11]));
                st_peer_f128(rb + 48, make_float4(nmB[12], nmB[13], nmB[14], nmB[15]));
            }
        }
        cluster_sync_();   // B4: out-LN partials + peer M halves visible

        if (ih == 0) {
            const float usum = sU[0] + eU[0], usq = sU[1] + eU[1];
            const float um = usum * (1.f / D_);
            const float uv = usq * (1.f / D_) - um * um;
            const float rr = rsqrtf(uv + EPSLN);
            float* po = out + ((size_t)t * B_ + b) * D_ + og;
            po[0] = (u0 - um) * rr * ongv.x + onbv.x;
            po[1] = (u1 - um) * rr * ongv.y + onbv.y;
        }
        __syncthreads();   // protect scat/sQ/sKv for next iteration
    }

    // proto = transpose(M, (1,0,2)) : [K, B, d]
    if (ih == 0) {
        #pragma unroll
        for (int j = 0; j < K_; ++j) {
            out[(size_t)S_ * B_ * D_ + ((size_t)j * B_ + b) * D_ + og]     = sM[og][j];
            out[(size_t)S_ * B_ * D_ + ((size_t)j * B_ + b) * D_ + og + 1] = sM[og + 1][j];
        }
    }
}

extern "C" void kernel_launch(void* const* d_in, const int* in_sizes, int n_in,
                              void* d_out, int out_size) {
    (void)in_sizes; (void)n_in; (void)out_size;
    memunit_kernel<<<2 * B_, NT>>>(
        (const float*)d_in[0],  (const float*)d_in[1],
        (const float*)d_in[2],  (const float*)d_in[3],
        (const float*)d_in[4],  (const float*)d_in[5],
        (const float*)d_in[6],  (const float*)d_in[7],
        (const float*)d_in[8],  (const float*)d_in[9],
        (const float*)d_in[10], (const float*)d_in[11],
        (const float*)d_in[12], (const float*)d_in[13],
        (const float*)d_in[14], (const float*)d_in[15],
        (const float*)d_in[16], (const float*)d_in[17],
        (const float*)d_in[18], (const float*)d_in[19],
        (const float*)d_in[20], (const float*)d_in[21],
        (const float*)d_in[22], (const float*)d_in[23],
        (float*)d_out);
}

// round 7
// speedup vs baseline: 1.0221x; 1.0221x over previous
#include <cuda_runtime.h>
#include <math.h>
#include <stdint.h>

// MemoryUnit, Round 6: 2-CTA cluster per batch element, algebraic k/v
// elimination (logits = M@(Wk q), r = (attn@M)@Wv + bv), register-pressure
// fix vs R5: 4-deep load batches, g/erase staged in SMEM, flat memory-update
// pass, q.bk dropped (softmax shift invariance).

namespace {
constexpr int S_ = 2048;
constexpr int B_ = 64;
constexpr int D_ = 256;
constexpr int K_ = 16;
constexpr int NT = 256;
constexpr float EPSLN = 1e-5f;
constexpr float MOMC  = 0.9f;

__device__ __forceinline__ float geluf(float v) {
    return 0.5f * v * (1.0f + erff(v * 0.70710678118654752440f));
}
__device__ __forceinline__ float sigmf(float v) {
    return 1.0f / (1.0f + expf(-v));
}
__device__ __forceinline__ uint32_t smem_u32(const void* p) {
    return (uint32_t)__cvta_generic_to_shared(const_cast<void*>(p));
}
__device__ __forceinline__ uint32_t peer_addr(uint32_t la, uint32_t peer) {
    uint32_t ra;
    asm("mapa.shared::cluster.u32 %0, %1, %2;" : "=r"(ra) : "r"(la), "r"(peer));
    return ra;
}
__device__ __forceinline__ void st_peer_f32(uint32_t ra, float v) {
    asm volatile("st.shared::cluster.f32 [%0], %1;" :: "r"(ra), "f"(v) : "memory");
}
__device__ __forceinline__ void st_peer_f64(uint32_t ra, float a, float b) {
    asm volatile("st.shared::cluster.v2.f32 [%0], {%1,%2};"
                 :: "r"(ra), "f"(a), "f"(b) : "memory");
}
__device__ __forceinline__ void st_peer_f128(uint32_t ra, float4 v) {
    asm volatile("st.shared::cluster.v4.f32 [%0], {%1,%2,%3,%4};"
                 :: "r"(ra), "f"(v.x), "f"(v.y), "f"(v.z), "f"(v.w) : "memory");
}
__device__ __forceinline__ void cluster_sync_() {
    asm volatile("barrier.cluster.arrive.aligned;\n\t"
                 "barrier.cluster.wait.aligned;" ::: "memory");
}
__device__ __forceinline__ float2 ld2(const float* p) {
    return *reinterpret_cast<const float2*>(p);
}
__device__ __forceinline__ float red4(float v) {
    v += __shfl_xor_sync(0xffffffffu, v, 1);
    v += __shfl_xor_sync(0xffffffffu, v, 2);
    return v;
}
} // namespace

__global__ __launch_bounds__(NT, 1) __cluster_dims__(2, 1, 1)
void memunit_kernel(
    const float* __restrict__ x,     const float* __restrict__ slot_init,
    const float* __restrict__ Wq,    const float* __restrict__ bq,
    const float* __restrict__ Wk,    const float* __restrict__ bk,
    const float* __restrict__ Wv,    const float* __restrict__ bv,
    const float* __restrict__ wg1W,  const float* __restrict__ wg1b,
    const float* __restrict__ wg2W,  const float* __restrict__ wg2b,
    const float* __restrict__ egW,   const float* __restrict__ egb,
    const float* __restrict__ wcW,   const float* __restrict__ wcb,
    const float* __restrict__ wclng, const float* __restrict__ wclnb,
    const float* __restrict__ fuW,   const float* __restrict__ fub,
    const float* __restrict__ fulng, const float* __restrict__ fulnb,
    const float* __restrict__ ong,   const float* __restrict__ onb,
    float* __restrict__ out)
{
    __shared__ float sM[D_][K_];       // full M, feature-major, peer-mirrored
    __shared__ float scat[2 * D_];     // [x_t | r]
    __shared__ float sQ[D_];           // full q (with bias)
    __shared__ float sKv[128];         // Wk @ q for my CTA's 128 i-rows
    __shared__ float sMbar[D_];        // attn-weighted slot average
    __shared__ float sG[128][K_];      // gelu(write pre-act) per (local o, slot)
    __shared__ float sE[128][K_];      // sigmoid(erase pre-act)
    __shared__ float sCg[128], sCb[128]; // wc_ln gamma/beta for my rows
    __shared__ float sLP[4][K_];       // logit warp partials
    __shared__ float sGP[8][2 * K_];   // gstat warp partials
    __shared__ float sGloc[2 * K_], eG[2 * K_];
    __shared__ float sLoc[K_], eL[K_];
    __shared__ float sBR[8][3];
    __shared__ float sF[3], eF[3], sU[2], eU[2];
    __shared__ float sAttn[K_], sEvict[K_], sPers[K_], sMean[K_], sRstd[K_];
    __shared__ float sNov;

    const int tid  = threadIdx.x;
    const int lane = tid & 31;
    const int wid  = tid >> 5;
    const int ih   = tid & 3;          // i-quarter
    const int op   = tid >> 2;         // o-pair 0..63
    uint32_t rank;
    asm("mov.u32 %0, %%cluster_ctarank;" : "=r"(rank));
    const uint32_t peer = rank ^ 1u;
    const int b  = blockIdx.x >> 1;
    const int og = (int)rank * 128 + op * 2;

    #pragma unroll
    for (int j = 0; j < K_; ++j) sM[tid][j] = slot_init[j * D_ + tid];
    if (tid < K_) sPers[tid] = 0.f;
    if (tid < 128) {
        const int grow = (int)rank * 128 + tid;
        sCg[tid] = wclng[grow];
        sCb[tid] = wclnb[grow];
    }

    const float2 bqv = ld2(bq + og), bvv = ld2(bv + og);
    const float2 egbv = ld2(egb + og), wcbv = ld2(wcb + og);
    const float2 fubv = ld2(fub + og), fulngv = ld2(fulng + og), fulnbv = ld2(fulnb + og);
    const float2 wg1bv = ld2(wg1b + og), wg2wv = ld2(wg2W + og);
    const float  wg2b0 = wg2b[0];
    const float2 ongv = ld2(ong + og), onbv = ld2(onb + og);

    for (int t = 0; t < S_; ++t) {
        scat[tid] = x[((size_t)t * B_ + b) * D_ + tid];
        __syncthreads();

        const int i0 = ih * 64;

        // ---- q = x @ Wq + bq (i-quarter split, batch 8) ----
        float q0 = 0.f, q1 = 0.f;
        for (int c = 0; c < 64; c += 8) {
            float2 w[8];
            #pragma unroll
            for (int u = 0; u < 8; ++u) w[u] = ld2(Wq + (i0 + c + u) * D_ + og);
            #pragma unroll
            for (int u = 0; u < 8; ++u) {
                const float xv = scat[i0 + c + u];
                q0 = fmaf(xv, w[u].x, q0);
                q1 = fmaf(xv, w[u].y, q1);
            }
        }
        q0 = red4(q0) + bqv.x;
        q1 = red4(q1) + bqv.y;
        if (ih == 0)      { sQ[og] = q0; sQ[og + 1] = q1; }
        else if (ih == 1) st_peer_f64(peer_addr(smem_u32(&sQ[og]), peer), q0, q1);

        // ---- eg/wc GEMM over my i-quarter (batch 4) ----
        float ae0[K_], ae1[K_], aw0[K_], aw1[K_];
        float ce0 = 0.f, ce1 = 0.f, cw0 = 0.f, cw1 = 0.f;
        #pragma unroll
        for (int j = 0; j < K_; ++j) { ae0[j]=0.f; ae1[j]=0.f; aw0[j]=0.f; aw1[j]=0.f; }
        for (int c = 0; c < 64; c += 4) {
            float2 vEL[4], vEH[4], vWL[4], vWH[4];
            #pragma unroll
            for (int u = 0; u < 4; ++u) {
                const int lo = (i0 + c + u) * D_ + og;
                vEL[u] = ld2(egW + lo); vEH[u] = ld2(egW + lo + D_ * D_);
                vWL[u] = ld2(wcW + lo); vWH[u] = ld2(wcW + lo + D_ * D_);
            }
            #pragma unroll
            for (int u = 0; u < 4; ++u) {
                const int i = i0 + c + u;
                const float xv = scat[i];
                const float4* mr = reinterpret_cast<const float4*>(sM[i]);
                const float4 m0 = mr[0], m1 = mr[1], m2 = mr[2], m3 = mr[3];
                ce0 = fmaf(xv, vEL[u].x, ce0); ce1 = fmaf(xv, vEL[u].y, ce1);
                cw0 = fmaf(xv, vWL[u].x, cw0); cw1 = fmaf(xv, vWL[u].y, cw1);
                const float mv[K_] = {m0.x,m0.y,m0.z,m0.w, m1.x,m1.y,m1.z,m1.w,
                                      m2.x,m2.y,m2.z,m2.w, m3.x,m3.y,m3.z,m3.w};
                #pragma unroll
                for (int j = 0; j < K_; ++j) {
                    ae0[j] = fmaf(mv[j], vEH[u].x, ae0[j]);
                    ae1[j] = fmaf(mv[j], vEH[u].y, ae1[j]);
                    aw0[j] = fmaf(mv[j], vWH[u].x, aw0[j]);
                    aw1[j] = fmaf(mv[j], vWH[u].y, aw1[j]);
                }
            }
        }
        ce0 = red4(ce0); ce1 = red4(ce1); cw0 = red4(cw0); cw1 = red4(cw1);
        #pragma unroll
        for (int j = 0; j < K_; ++j) {
            ae0[j] = red4(ae0[j]); ae1[j] = red4(ae1[j]);
            aw0[j] = red4(aw0[j]); aw1[j] = red4(aw1[j]);
        }

        if (ih == 0) {
            // write-candidate gelu + LN partials; masked butterfly over ih0 lanes
            float g0[K_], g1[K_], gs[K_], gq[K_];
            #pragma unroll
            for (int j = 0; j < K_; ++j) {
                g0[j] = geluf(aw0[j] + cw0 + wcbv.x);
                g1[j] = geluf(aw1[j] + cw1 + wcbv.y);
                gs[j] = g0[j] + g1[j];
                gq[j] = g0[j] * g0[j] + g1[j] * g1[j];
            }
            #pragma unroll
            for (int off = 4; off <= 16; off <<= 1) {
                #pragma unroll
                for (int j = 0; j < K_; ++j) {
                    gs[j] += __shfl_xor_sync(0x11111111u, gs[j], off);
                    gq[j] += __shfl_xor_sync(0x11111111u, gq[j], off);
                }
            }
            if (lane == 0) {
                #pragma unroll
                for (int j = 0; j < K_; ++j) {
                    sGP[wid][j] = gs[j];
                    sGP[wid][K_ + j] = gq[j];
                }
            }
            float4* ga = reinterpret_cast<float4*>(sG[op * 2]);
            float4* gb = reinterpret_cast<float4*>(sG[op * 2 + 1]);
            ga[0] = make_float4(g0[0], g0[1], g0[2], g0[3]);
            ga[1] = make_float4(g0[4], g0[5], g0[6], g0[7]);
            ga[2] = make_float4(g0[8], g0[9], g0[10], g0[11]);
            ga[3] = make_float4(g0[12], g0[13], g0[14], g0[15]);
            gb[0] = make_float4(g1[0], g1[1], g1[2], g1[3]);
            gb[1] = make_float4(g1[4], g1[5], g1[6], g1[7]);
            gb[2] = make_float4(g1[8], g1[9], g1[10], g1[11]);
            gb[3] = make_float4(g1[12], g1[13], g1[14], g1[15]);
        } else if (ih == 1) {
            // erase sigmoids
            float e0[K_], e1[K_];
            #pragma unroll
            for (int j = 0; j < K_; ++j) {
                e0[j] = sigmf(ae0[j] + ce0 + egbv.x);
                e1[j] = sigmf(ae1[j] + ce1 + egbv.y);
            }
            float4* ea = reinterpret_cast<float4*>(sE[op * 2]);
            float4* eb = reinterpret_cast<float4*>(sE[op * 2 + 1]);
            ea[0] = make_float4(e0[0], e0[1], e0[2], e0[3]);
            ea[1] = make_float4(e0[4], e0[5], e0[6], e0[7]);
            ea[2] = make_float4(e0[8], e0[9], e0[10], e0[11]);
            ea[3] = make_float4(e0[12], e0[13], e0[14], e0[15]);
            eb[0] = make_float4(e1[0], e1[1], e1[2], e1[3]);
            eb[1] = make_float4(e1[4], e1[5], e1[6], e1[7]);
            eb[2] = make_float4(e1[8], e1[9], e1[10], e1[11]);
            eb[3] = make_float4(e1[12], e1[13], e1[14], e1[15]);
        }
        cluster_sync_();   // B0: full q visible; local sG/sE/sGP committed

        // ---- Kvec_i = sum_o Wk[i,o] q_o for my 128 i-rows ----
        {
            const int e  = tid >> 1;
            const int oh = tid & 1;
            const float4* wr = reinterpret_cast<const float4*>(
                Wk + (size_t)((int)rank * 128 + e) * D_ + oh * 128);
            const float4* qv = reinterpret_cast<const float4*>(sQ + oh * 128);
            float acc = 0.f;
            #pragma unroll
            for (int u = 0; u < 32; ++u) {
                const float4 w4 = wr[u];
                const float4 q4 = qv[u];
                acc = fmaf(w4.x, q4.x, acc);
                acc = fmaf(w4.y, q4.y, acc);
                acc = fmaf(w4.z, q4.z, acc);
                acc = fmaf(w4.w, q4.w, acc);
            }
            acc += __shfl_xor_sync(0xffffffffu, acc, 1);
            if (oh == 0) sKv[e] = acc;
        }
        __syncthreads();

        // ---- logit partials over my 128 i-rows ----
        if (tid < 128) {
            const int gi = (int)rank * 128 + tid;
            const float kv = sKv[tid];
            const float4* mr = reinterpret_cast<const float4*>(sM[gi]);
            const float4 m0 = mr[0], m1 = mr[1], m2 = mr[2], m3 = mr[3];
            const float mv[K_] = {m0.x,m0.y,m0.z,m0.w, m1.x,m1.y,m1.z,m1.w,
                                  m2.x,m2.y,m2.z,m2.w, m3.x,m3.y,m3.z,m3.w};
            float p[K_];
            #pragma unroll
            for (int j = 0; j < K_; ++j) p[j] = mv[j] * kv;
            #pragma unroll
            for (int off = 1; off < 32; off <<= 1) {
                #pragma unroll
                for (int j = 0; j < K_; ++j)
                    p[j] += __shfl_xor_sync(0xffffffffu, p[j], off);
            }
            if (lane == 0) {
                #pragma unroll
                for (int j = 0; j < K_; ++j) sLP[wid][j] = p[j];
            }
        }
        __syncthreads();
        if (tid < K_) {
            const float s = sLP[0][tid] + sLP[1][tid] + sLP[2][tid] + sLP[3][tid];
            sLoc[tid] = s;
            st_peer_f32(peer_addr(smem_u32(&eL[tid]), peer), s);
        }
        cluster_sync_();   // B1: logit halves exchanged

        // ---- softmax / pers / evict (q.bk dropped: softmax shift-invariant) ----
        if (tid < K_) {
            float l = (sLoc[tid] + eL[tid]) * 0.0625f;
            float mx = l;
            #pragma unroll
            for (int off = 8; off; off >>= 1) mx = fmaxf(mx, __shfl_xor_sync(0xffffu, mx, off, 16));
            const float e = expf(l - mx);
            float s = e;
            #pragma unroll
            for (int off = 8; off; off >>= 1) s += __shfl_xor_sync(0xffffu, s, off, 16);
            const float a = e / s;
            sAttn[tid] = a;
            if (tid == 0) sNov = 1.f - 1.f / s;
            const float pr = MOMC * sPers[tid] + (1.f - MOMC) * a;
            sPers[tid] = pr;
            float el = -4.f * pr, em = el;
            #pragma unroll
            for (int off = 8; off; off >>= 1) em = fmaxf(em, __shfl_xor_sync(0xffffu, em, off, 16));
            const float ee = expf(el - em);
            float es = ee;
            #pragma unroll
            for (int off = 8; off; off >>= 1) es += __shfl_xor_sync(0xffffu, es, off, 16);
            sEvict[tid] = ee / es;
        }
        __syncthreads();

        // ---- m-bar = attn @ M ----
        {
            const float4* mr = reinterpret_cast<const float4*>(sM[tid]);
            const float4 m0 = mr[0], m1 = mr[1], m2 = mr[2], m3 = mr[3];
            const float mv[K_] = {m0.x,m0.y,m0.z,m0.w, m1.x,m1.y,m1.z,m1.w,
                                  m2.x,m2.y,m2.z,m2.w, m3.x,m3.y,m3.z,m3.w};
            float acc = 0.f;
            #pragma unroll
            for (int j = 0; j < K_; ++j) acc = fmaf(sAttn[j], mv[j], acc);
            sMbar[tid] = acc;
        }
        __syncthreads();

        // ---- r = m-bar @ Wv + bv (batch 8) ----
        float r0 = 0.f, r1 = 0.f;
        for (int c = 0; c < 64; c += 8) {
            float2 w[8];
            #pragma unroll
            for (int u = 0; u < 8; ++u) w[u] = ld2(Wv + (i0 + c + u) * D_ + og);
            #pragma unroll
            for (int u = 0; u < 8; ++u) {
                const float mb = sMbar[i0 + c + u];
                r0 = fmaf(mb, w[u].x, r0);
                r1 = fmaf(mb, w[u].y, r1);
            }
        }
        r0 = red4(r0) + bvv.x;
        r1 = red4(r1) + bvv.y;
        if (ih == 0)      { scat[D_ + og] = r0; scat[D_ + og + 1] = r1; }
        else if (ih == 1) st_peer_f64(peer_addr(smem_u32(&scat[D_ + og]), peer), r0, r1);
        // gstat combine + exchange
        if (tid < 2 * K_) {
            float s = 0.f;
            #pragma unroll
            for (int w = 0; w < 8; ++w) s += sGP[w][tid];
            sGloc[tid] = s;
            st_peer_f32(peer_addr(smem_u32(&eG[tid]), peer), s);
        }
        cluster_sync_();   // B2: cat complete + gstats exchanged

        if (tid < K_) {
            const float gsum = sGloc[tid] + eG[tid];
            const float gsq  = sGloc[K_ + tid] + eG[K_ + tid];
            const float mean = gsum * (1.f / D_);
            const float var  = gsq * (1.f / D_) - mean * mean;
            sMean[tid] = mean;
            sRstd[tid] = rsqrtf(var + EPSLN);
        }

        // ---- fu / wg1 over cat (i-quarter of 512, batch 8) ----
        float af0 = 0.f, af1 = 0.f, ag0 = 0.f, ag1 = 0.f;
        const int c0 = ih * 128;
        for (int c = 0; c < 128; c += 8) {
            float2 vF[8], vG[8];
            #pragma unroll
            for (int u = 0; u < 8; ++u) {
                const int wix = (c0 + c + u) * D_ + og;
                vF[u] = ld2(fuW + wix);
                vG[u] = ld2(wg1W + wix);
            }
            #pragma unroll
            for (int u = 0; u < 8; ++u) {
                const float cv = scat[c0 + c + u];
                af0 = fmaf(cv, vF[u].x, af0); af1 = fmaf(cv, vF[u].y, af1);
                ag0 = fmaf(cv, vG[u].x, ag0); ag1 = fmaf(cv, vG[u].y, ag1);
            }
        }
        af0 = red4(af0); af1 = red4(af1);
        ag0 = red4(ag0); ag1 = red4(ag1);
        const float hf0 = geluf(af0 + fubv.x);
        const float hf1 = geluf(af1 + fubv.y);
        const float hg0 = geluf(ag0 + wg1bv.x);
        const float hg1 = geluf(ag1 + wg1bv.y);
        {
            float a0 = hf0 + hf1;
            float a1 = hf0 * hf0 + hf1 * hf1;
            float a2 = hg0 * wg2wv.x + hg1 * wg2wv.y;
            #pragma unroll
            for (int off = 4; off <= 16; off <<= 1) {
                a0 += __shfl_xor_sync(0xffffffffu, a0, off);
                a1 += __shfl_xor_sync(0xffffffffu, a1, off);
                a2 += __shfl_xor_sync(0xffffffffu, a2, off);
            }
            if (lane == 0) { sBR[wid][0] = a0; sBR[wid][1] = a1; sBR[wid][2] = a2; }
        }
        __syncthreads();   // sBR + sMean/sRstd ready
        if (tid < 3) {
            float s = 0.f;
            #pragma unroll
            for (int w = 0; w < 8; ++w) s += sBR[w][tid];
            sF[tid] = s;
            st_peer_f32(peer_addr(smem_u32(&eF[tid]), peer), s);
        }
        cluster_sync_();   // B3: fu-LN + wg2 partials exchanged

        const float fsum = sF[0] + eF[0], fsq = sF[1] + eF[1], wgs = sF[2] + eF[2];
        const float fmn = fsum * (1.f / D_);
        const float fvr = fsq * (1.f / D_) - fmn * fmn;
        const float frs = rsqrtf(fvr + EPSLN);
        const float outt0 = (hf0 - fmn) * frs * fulngv.x + fulnbv.x;
        const float outt1 = (hf1 - fmn) * frs * fulngv.y + fulnbv.y;
        const float gw = sigmf(wgs + wg2b0) * sNov;
        if (tid < K_) sPers[tid] += sEvict[tid] * gw * 0.1f;

        const float u0 = outt0 + scat[og];
        const float u1 = outt1 + scat[og + 1];
        {
            float b0 = u0 + u1;
            float b1 = u0 * u0 + u1 * u1;
            #pragma unroll
            for (int off = 4; off <= 16; off <<= 1) {
                b0 += __shfl_xor_sync(0xffffffffu, b0, off);
                b1 += __shfl_xor_sync(0xffffffffu, b1, off);
            }
            if (lane == 0) { sBR[wid][0] = b0; sBR[wid][1] = b1; }
        }
        __syncthreads();
        if (tid < 2) {
            float s = 0.f;
            #pragma unroll
            for (int w = 0; w < 8; ++w) s += sBR[w][tid];
            sU[tid] = s;
            st_peer_f32(peer_addr(smem_u32(&eU[tid]), peer), s);
        }

        // ---- memory update: flat smem pass, 8 cells/thread ----
        {
            const int rl = tid >> 1;          // local row 0..127
            const int ch = (tid & 1) * 8;     // col base
            const int grow = (int)rank * 128 + rl;
            const float cg = sCg[rl], cb = sCb[rl];
            float nm[8];
            #pragma unroll
            for (int c = 0; c < 8; ++c) {
                const int j = ch + c;
                const float al = gw * sEvict[j];
                const float wr = (sG[rl][j] - sMean[j]) * sRstd[j] * cg + cb;
                nm[c] = sM[grow][j] * (1.f - al * sE[rl][j]) + al * wr;
            }
            float4* rowp = reinterpret_cast<float4*>(&sM[grow][ch]);
            rowp[0] = make_float4(nm[0], nm[1], nm[2], nm[3]);
            rowp[1] = make_float4(nm[4], nm[5], nm[6], nm[7]);
            uint32_t ra = peer_addr(smem_u32(&sM[grow][ch]), peer);
            st_peer_f128(ra,      make_float4(nm[0], nm[1], nm[2], nm[3]));
            st_peer_f128(ra + 16, make_float4(nm[4], nm[5], nm[6], nm[7]));
        }
        cluster_sync_();   // B4: out-LN partials + peer M halves visible

        if (ih == 0) {
            const float usum = sU[0] + eU[0], usq = sU[1] + eU[1];
            const float um = usum * (1.f / D_);
            const float uv = usq * (1.f / D_) - um * um;
            const float rr = rsqrtf(uv + EPSLN);
            float* po = out + ((size_t)t * B_ + b) * D_ + og;
            po[0] = (u0 - um) * rr * ongv.x + onbv.x;
            po[1] = (u1 - um) * rr * ongv.y + onbv.y;
        }
    }

    __syncthreads();
    // proto = transpose(M, (1,0,2)) : [K, B, d]
    if (ih == 0) {
        #pragma unroll
        for (int j = 0; j < K_; ++j) {
            out[(size_t)S_ * B_ * D_ + ((size_t)j * B_ + b) * D_ + og]     = sM[og][j];
            out[(size_t)S_ * B_ * D_ + ((size_t)j * B_ + b) * D_ + og + 1] = sM[og + 1][j];
        }
    }
}

extern "C" void kernel_launch(void* const* d_in, const int* in_sizes, int n_in,
                              void* d_out, int out_size) {
    (void)in_sizes; (void)n_in; (void)out_size;
    memunit_kernel<<<2 * B_, NT>>>(
        (const float*)d_in[0],  (const float*)d_in[1],
        (const float*)d_in[2],  (const float*)d_in[3],
        (const float*)d_in[4],  (const float*)d_in[5],
        (const float*)d_in[6],  (const float*)d_in[7],
        (const float*)d_in[8],  (const float*)d_in[9],
        (const float*)d_in[10], (const float*)d_in[11],
        (const float*)d_in[12], (const float*)d_in[13],
        (const float*)d_in[14], (const float*)d_in[15],
        (const float*)d_in[16], (const float*)d_in[17],
        (const float*)d_in[18], (const float*)d_in[19],
        (const float*)d_in[20], (const float*)d_in[21],
        (const float*)d_in[22], (const float*)d_in[23],
        (float*)d_out);
}

// round 8
// speedup vs baseline: 1.8496x; 1.8096x over previous
#include <cuda_runtime.h>
#include <math.h>
#include <stdint.h>

// MemoryUnit, Round 7: 2-CTA cluster per batch element.
// Warp specialization: A (warps 0-3) = serial chain q->Kvec->logits->softmax->
// mbar->r->fu->LN; B (warps 4-7) = eg/wc GEMM (chunked between barriers) + M update.
// Memory shape: R4-style o-pair map (2 lines per LDG.64, 100% line use).

namespace {
constexpr int S_ = 2048;
constexpr int B_ = 64;
constexpr int D_ = 256;
constexpr int K_ = 16;
constexpr int NT = 256;
constexpr float EPSLN = 1e-5f;
constexpr float MOMC  = 0.9f;

__device__ __forceinline__ float geluf(float v) {
    return 0.5f * v * (1.0f + erff(v * 0.70710678118654752440f));
}
__device__ __forceinline__ float sigmf(float v) {
    return 1.0f / (1.0f + expf(-v));
}
__device__ __forceinline__ uint32_t smem_u32(const void* p) {
    return (uint32_t)__cvta_generic_to_shared(const_cast<void*>(p));
}
__device__ __forceinline__ uint32_t peer_addr(uint32_t la, uint32_t peer) {
    uint32_t ra;
    asm("mapa.shared::cluster.u32 %0, %1, %2;" : "=r"(ra) : "r"(la), "r"(peer));
    return ra;
}
__device__ __forceinline__ void st_peer_f32(uint32_t ra, float v) {
    asm volatile("st.shared::cluster.f32 [%0], %1;" :: "r"(ra), "f"(v) : "memory");
}
__device__ __forceinline__ void st_peer_f64(uint32_t ra, float a, float b) {
    asm volatile("st.shared::cluster.v2.f32 [%0], {%1,%2};"
                 :: "r"(ra), "f"(a), "f"(b) : "memory");
}
__device__ __forceinline__ void st_peer_f128(uint32_t ra, float4 v) {
    asm volatile("st.shared::cluster.v4.f32 [%0], {%1,%2,%3,%4};"
                 :: "r"(ra), "f"(v.x), "f"(v.y), "f"(v.z), "f"(v.w) : "memory");
}
__device__ __forceinline__ void cluster_sync_() {
    asm volatile("barrier.cluster.arrive.aligned;\n\t"
                 "barrier.cluster.wait.aligned;" ::: "memory");
}
__device__ __forceinline__ void barA() {   // group A (tid 0..127)
    asm volatile("bar.sync 1, 128;" ::: "memory");
}
__device__ __forceinline__ void barB() {   // group B (tid 128..255)
    asm volatile("bar.sync 2, 128;" ::: "memory");
}
__device__ __forceinline__ float2 ld2(const float* p) {
    return *reinterpret_cast<const float2*>(p);
}
} // namespace

__global__ __launch_bounds__(NT, 1) __cluster_dims__(2, 1, 1)
void memunit_kernel(
    const float* __restrict__ x,     const float* __restrict__ slot_init,
    const float* __restrict__ Wq,    const float* __restrict__ bq,
    const float* __restrict__ Wk,    const float* __restrict__ bk,
    const float* __restrict__ Wv,    const float* __restrict__ bv,
    const float* __restrict__ wg1W,  const float* __restrict__ wg1b,
    const float* __restrict__ wg2W,  const float* __restrict__ wg2b,
    const float* __restrict__ egW,   const float* __restrict__ egb,
    const float* __restrict__ wcW,   const float* __restrict__ wcb,
    const float* __restrict__ wclng, const float* __restrict__ wclnb,
    const float* __restrict__ fuW,   const float* __restrict__ fub,
    const float* __restrict__ fulng, const float* __restrict__ fulnb,
    const float* __restrict__ ong,   const float* __restrict__ onb,
    float* __restrict__ out)
{
    __shared__ float sM[D_][K_];       // full M, feature-major, peer-mirrored
    __shared__ float scat[2 * D_];     // [x_t | r]
    __shared__ float sQ[D_];           // full q (with bias)
    __shared__ float sKv[128];         // Wk @ q for my CTA's 128 i-rows
    __shared__ float sMbar[D_];        // attn-weighted slot average
    __shared__ float sG[128][K_];      // gelu(write pre-act), local-o rows
    __shared__ float sE[128][K_];      // sigmoid(erase pre-act)
    __shared__ float sLP[4][K_];       // A: logit warp partials
    __shared__ float sGP[4][2 * K_];   // B: gstat warp partials
    __shared__ float sGloc[2 * K_], eG[2 * K_];
    __shared__ float sLoc[K_], eL[K_];
    __shared__ float sFB[64][4];       // B's fu/wg1 half partials
    __shared__ float sBR[4][3];
    __shared__ float sF[3], eF[3], sU[2], eU[2];
    __shared__ float sAttn[K_], sEvict[K_], sPers[K_], sMean[K_], sRstd[K_];
    __shared__ float sNov;

    const int tid  = threadIdx.x;
    const int lane = tid & 31;
    const int wid  = tid >> 5;
    const bool isA = tid < 128;
    const int gt   = tid & 127;
    const int ih   = gt & 1;           // i-half within the group's range
    const int op   = gt >> 1;          // o-pair 0..63
    uint32_t rank;
    asm("mov.u32 %0, %%cluster_ctarank;" : "=r"(rank));
    const uint32_t peer = rank ^ 1u;
    const int b  = blockIdx.x >> 1;
    const int og = (int)rank * 128 + op * 2;

    #pragma unroll
    for (int j = 0; j < K_; ++j) sM[tid][j] = slot_init[j * D_ + tid];
    if (tid < K_) sPers[tid] = 0.f;

    // constants (loaded by both groups; each uses its subset)
    const float2 bqv = ld2(bq + og), bvv = ld2(bv + og);
    const float2 egbv = ld2(egb + og), wcbv = ld2(wcb + og);
    const float2 fubv = ld2(fub + og), fulngv = ld2(fulng + og), fulnbv = ld2(fulnb + og);
    const float2 wg1bv = ld2(wg1b + og), wg2wv = ld2(wg2W + og);
    const float  wg2b0 = wg2b[0];
    const float2 ongv = ld2(ong + og), onbv = ld2(onb + og);
    // B's memory-update row constants
    const int   grow = (int)rank * 128 + gt;
    const float cgB = wclng[grow], cbB = wclnb[grow];
    __syncthreads();

    for (int t = 0; t < S_; ++t) {
        scat[tid] = x[((size_t)t * B_ + b) * D_ + tid];
        __syncthreads();

        // B accumulators (live across phases)
        float ae0[K_], ae1[K_], aw0[K_], aw1[K_];
        float ce0 = 0.f, ce1 = 0.f, cw0 = 0.f, cw1 = 0.f;
        #pragma unroll
        for (int j = 0; j < K_; ++j) { ae0[j]=0.f; ae1[j]=0.f; aw0[j]=0.f; aw1[j]=0.f; }

        // eg/wc chunk: i in [i0 + c0, i0 + c1), R4-style 2-line loads
        auto egwc = [&](int c0, int c1) {
            const int i0 = ih << 7;
            for (int c = c0; c < c1; c += 4) {
                float2 vEL[4], vEH[4], vWL[4], vWH[4];
                #pragma unroll
                for (int u = 0; u < 4; ++u) {
                    const int lo = (i0 + c + u) * D_ + og;
                    vEL[u] = ld2(egW + lo); vEH[u] = ld2(egW + lo + D_ * D_);
                    vWL[u] = ld2(wcW + lo); vWH[u] = ld2(wcW + lo + D_ * D_);
                }
                #pragma unroll
                for (int u = 0; u < 4; ++u) {
                    const int i = i0 + c + u;
                    const float xv = scat[i];
                    const float4* mr = reinterpret_cast<const float4*>(sM[i]);
                    const float4 m0 = mr[0], m1 = mr[1], m2 = mr[2], m3 = mr[3];
                    ce0 = fmaf(xv, vEL[u].x, ce0); ce1 = fmaf(xv, vEL[u].y, ce1);
                    cw0 = fmaf(xv, vWL[u].x, cw0); cw1 = fmaf(xv, vWL[u].y, cw1);
                    const float mv[K_] = {m0.x,m0.y,m0.z,m0.w, m1.x,m1.y,m1.z,m1.w,
                                          m2.x,m2.y,m2.z,m2.w, m3.x,m3.y,m3.z,m3.w};
                    #pragma unroll
                    for (int j = 0; j < K_; ++j) {
                        ae0[j] = fmaf(mv[j], vEH[u].x, ae0[j]);
                        ae1[j] = fmaf(mv[j], vEH[u].y, ae1[j]);
                        aw0[j] = fmaf(mv[j], vWH[u].x, aw0[j]);
                        aw1[j] = fmaf(mv[j], vWH[u].y, aw1[j]);
                    }
                }
            }
        };

        // ================= PHASE 0 =================
        if (isA) {
            // q = x @ Wq + bq over my i-half
            float q0 = 0.f, q1 = 0.f;
            const int i0 = ih << 7;
            for (int c = 0; c < 128; c += 8) {
                float2 w[8];
                #pragma unroll
                for (int u = 0; u < 8; ++u) w[u] = ld2(Wq + (i0 + c + u) * D_ + og);
                #pragma unroll
                for (int u = 0; u < 8; ++u) {
                    const float xv = scat[i0 + c + u];
                    q0 = fmaf(xv, w[u].x, q0);
                    q1 = fmaf(xv, w[u].y, q1);
                }
            }
            q0 += __shfl_xor_sync(0xffffffffu, q0, 1);
            q1 += __shfl_xor_sync(0xffffffffu, q1, 1);
            q0 += bqv.x; q1 += bqv.y;
            if (ih == 0) { sQ[og] = q0; sQ[og + 1] = q1; }
            else st_peer_f64(peer_addr(smem_u32(&sQ[og]), peer), q0, q1);
        } else {
            egwc(0, 44);
        }
        cluster_sync_();   // B0: full q visible in both CTAs

        // ================= PHASE 1 =================
        if (isA) {
            // Kvec for my CTA's 128 i-rows: warp-per-row, lanes over o (coalesced)
            const float4 q4lo = reinterpret_cast<const float4*>(sQ)[lane];
            const float4 q4hi = reinterpret_cast<const float4*>(sQ)[lane + 32];
            for (int r = wid; r < 128; r += 4) {
                const float* wr = Wk + (size_t)((int)rank * 128 + r) * D_;
                const float4 wlo = reinterpret_cast<const float4*>(wr)[lane];
                const float4 whi = reinterpret_cast<const float4*>(wr)[lane + 32];
                float a = wlo.x * q4lo.x;
                a = fmaf(wlo.y, q4lo.y, a);
                a = fmaf(wlo.z, q4lo.z, a);
                a = fmaf(wlo.w, q4lo.w, a);
                a = fmaf(whi.x, q4hi.x, a);
                a = fmaf(whi.y, q4hi.y, a);
                a = fmaf(whi.z, q4hi.z, a);
                a = fmaf(whi.w, q4hi.w, a);
                #pragma unroll
                for (int off = 16; off; off >>= 1)
                    a += __shfl_xor_sync(0xffffffffu, a, off);
                if (lane == 0) sKv[r] = a;
            }
            barA();
            // logit partials: each A thread one i-row
            {
                const int gi = (int)rank * 128 + gt;
                const float kv = sKv[gt];
                const float4* mr = reinterpret_cast<const float4*>(sM[gi]);
                const float4 m0 = mr[0], m1 = mr[1], m2 = mr[2], m3 = mr[3];
                const float mv[K_] = {m0.x,m0.y,m0.z,m0.w, m1.x,m1.y,m1.z,m1.w,
                                      m2.x,m2.y,m2.z,m2.w, m3.x,m3.y,m3.z,m3.w};
                float p[K_];
                #pragma unroll
                for (int j = 0; j < K_; ++j) p[j] = mv[j] * kv;
                #pragma unroll
                for (int off = 1; off < 32; off <<= 1) {
                    #pragma unroll
                    for (int j = 0; j < K_; ++j)
                        p[j] += __shfl_xor_sync(0xffffffffu, p[j], off);
                }
                if (lane == 0) {
                    #pragma unroll
                    for (int j = 0; j < K_; ++j) sLP[wid][j] = p[j];
                }
            }
            barA();
            if (tid < K_) {
                const float s = sLP[0][tid] + sLP[1][tid] + sLP[2][tid] + sLP[3][tid];
                sLoc[tid] = s;
                st_peer_f32(peer_addr(smem_u32(&eL[tid]), peer), s);
            }
        } else {
            egwc(44, 88);
        }
        cluster_sync_();   // B1: logit halves exchanged

        // ================= PHASE 2 =================
        if (isA) {
            if (tid < K_) {
                float l = (sLoc[tid] + eL[tid]) * 0.0625f;   // * d^-0.5
                float mx = l;
                #pragma unroll
                for (int off = 8; off; off >>= 1) mx = fmaxf(mx, __shfl_xor_sync(0xffffu, mx, off, 16));
                const float e = expf(l - mx);
                float s = e;
                #pragma unroll
                for (int off = 8; off; off >>= 1) s += __shfl_xor_sync(0xffffu, s, off, 16);
                const float a = e / s;
                sAttn[tid] = a;
                if (tid == 0) sNov = 1.f - 1.f / s;
                const float pr = MOMC * sPers[tid] + (1.f - MOMC) * a;
                sPers[tid] = pr;
                float el = -4.f * pr, em = el;
                #pragma unroll
                for (int off = 8; off; off >>= 1) em = fmaxf(em, __shfl_xor_sync(0xffffu, em, off, 16));
                const float ee = expf(el - em);
                float es = ee;
                #pragma unroll
                for (int off = 8; off; off >>= 1) es += __shfl_xor_sync(0xffffu, es, off, 16);
                sEvict[tid] = ee / es;
            }
            barA();
            // m-bar = attn @ M  (2 features per A thread)
            #pragma unroll
            for (int h = 0; h < 2; ++h) {
                const int f = gt + h * 128;
                const float4* mr = reinterpret_cast<const float4*>(sM[f]);
                const float4 m0 = mr[0], m1 = mr[1], m2 = mr[2], m3 = mr[3];
                const float mv[K_] = {m0.x,m0.y,m0.z,m0.w, m1.x,m1.y,m1.z,m1.w,
                                      m2.x,m2.y,m2.z,m2.w, m3.x,m3.y,m3.z,m3.w};
                float acc = 0.f;
                #pragma unroll
                for (int j = 0; j < K_; ++j) acc = fmaf(sAttn[j], mv[j], acc);
                sMbar[f] = acc;
            }
            barA();
            // r = m-bar @ Wv + bv over my i-half
            float r0 = 0.f, r1 = 0.f;
            const int i0 = ih << 7;
            for (int c = 0; c < 128; c += 8) {
                float2 w[8];
                #pragma unroll
                for (int u = 0; u < 8; ++u) w[u] = ld2(Wv + (i0 + c + u) * D_ + og);
                #pragma unroll
                for (int u = 0; u < 8; ++u) {
                    const float mb = sMbar[i0 + c + u];
                    r0 = fmaf(mb, w[u].x, r0);
                    r1 = fmaf(mb, w[u].y, r1);
                }
            }
            r0 += __shfl_xor_sync(0xffffffffu, r0, 1);
            r1 += __shfl_xor_sync(0xffffffffu, r1, 1);
            r0 += bvv.x; r1 += bvv.y;
            if (ih == 0) { scat[D_ + og] = r0; scat[D_ + og + 1] = r1; }
            else st_peer_f64(peer_addr(smem_u32(&scat[D_ + og]), peer), r0, r1);
        } else {
            egwc(88, 128);
            // cross-ih pair reduce
            ce0 += __shfl_xor_sync(0xffffffffu, ce0, 1);
            ce1 += __shfl_xor_sync(0xffffffffu, ce1, 1);
            cw0 += __shfl_xor_sync(0xffffffffu, cw0, 1);
            cw1 += __shfl_xor_sync(0xffffffffu, cw1, 1);
            #pragma unroll
            for (int j = 0; j < K_; ++j) {
                ae0[j] += __shfl_xor_sync(0xffffffffu, ae0[j], 1);
                ae1[j] += __shfl_xor_sync(0xffffffffu, ae1[j], 1);
                aw0[j] += __shfl_xor_sync(0xffffffffu, aw0[j], 1);
                aw1[j] += __shfl_xor_sync(0xffffffffu, aw1[j], 1);
            }
            if (ih == 0) {
                // gelu write-candidate + LN stat partials (even lanes only)
                float g0[K_], g1[K_], gs[K_], gq[K_];
                #pragma unroll
                for (int j = 0; j < K_; ++j) {
                    g0[j] = geluf(aw0[j] + cw0 + wcbv.x);
                    g1[j] = geluf(aw1[j] + cw1 + wcbv.y);
                    gs[j] = g0[j] + g1[j];
                    gq[j] = g0[j] * g0[j] + g1[j] * g1[j];
                }
                #pragma unroll
                for (int off = 2; off <= 16; off <<= 1) {
                    #pragma unroll
                    for (int j = 0; j < K_; ++j) {
                        gs[j] += __shfl_xor_sync(0x55555555u, gs[j], off);
                        gq[j] += __shfl_xor_sync(0x55555555u, gq[j], off);
                    }
                }
                if (lane == 0) {
                    #pragma unroll
                    for (int j = 0; j < K_; ++j) {
                        sGP[wid - 4][j] = gs[j];
                        sGP[wid - 4][K_ + j] = gq[j];
                    }
                }
                float4* ga = reinterpret_cast<float4*>(sG[op * 2]);
                float4* gb = reinterpret_cast<float4*>(sG[op * 2 + 1]);
                ga[0] = make_float4(g0[0], g0[1], g0[2], g0[3]);
                ga[1] = make_float4(g0[4], g0[5], g0[6], g0[7]);
                ga[2] = make_float4(g0[8], g0[9], g0[10], g0[11]);
                ga[3] = make_float4(g0[12], g0[13], g0[14], g0[15]);
                gb[0] = make_float4(g1[0], g1[1], g1[2], g1[3]);
                gb[1] = make_float4(g1[4], g1[5], g1[6], g1[7]);
                gb[2] = make_float4(g1[8], g1[9], g1[10], g1[11]);
                gb[3] = make_float4(g1[12], g1[13], g1[14], g1[15]);
            } else {
                // erase sigmoids (odd lanes)
                float e0[K_], e1[K_];
                #pragma unroll
                for (int j = 0; j < K_; ++j) {
                    e0[j] = sigmf(ae0[j] + ce0 + egbv.x);
                    e1[j] = sigmf(ae1[j] + ce1 + egbv.y);
                }
                float4* ea = reinterpret_cast<float4*>(sE[op * 2]);
                float4* eb = reinterpret_cast<float4*>(sE[op * 2 + 1]);
                ea[0] = make_float4(e0[0], e0[1], e0[2], e0[3]);
                ea[1] = make_float4(e0[4], e0[5], e0[6], e0[7]);
                ea[2] = make_float4(e0[8], e0[9], e0[10], e0[11]);
                ea[3] = make_float4(e0[12], e0[13], e0[14], e0[15]);
                eb[0] = make_float4(e1[0], e1[1], e1[2], e1[3]);
                eb[1] = make_float4(e1[4], e1[5], e1[6], e1[7]);
                eb[2] = make_float4(e1[8], e1[9], e1[10], e1[11]);
                eb[3] = make_float4(e1[12], e1[13], e1[14], e1[15]);
            }
            barB();
            if (gt < 2 * K_) {
                const float s = sGP[0][gt] + sGP[1][gt] + sGP[2][gt] + sGP[3][gt];
                sGloc[gt] = s;
                st_peer_f32(peer_addr(smem_u32(&eG[gt]), peer), s);
            }
        }
        cluster_sync_();   // B2: cat complete + gstats exchanged

        // ================= PHASE 3 =================
        if (tid < K_) {
            const float gsum = sGloc[tid] + eG[tid];
            const float gsq  = sGloc[K_ + tid] + eG[K_ + tid];
            const float mean = gsum * (1.f / D_);
            const float var  = gsq * (1.f / D_) - mean * mean;
            sMean[tid] = mean;
            sRstd[tid] = rsqrtf(var + EPSLN);
        }
        // fu / wg1: A does cat[0..255], B does cat[256..511]
        float af0 = 0.f, af1 = 0.f, ag0 = 0.f, ag1 = 0.f;
        {
            const int base = isA ? 0 : 256;
            const int c0 = base + (ih << 7);
            for (int c = 0; c < 128; c += 8) {
                float2 vF[8], vG[8];
                #pragma unroll
                for (int u = 0; u < 8; ++u) {
                    const int wix = (c0 + c + u) * D_ + og;
                    vF[u] = ld2(fuW + wix);
                    vG[u] = ld2(wg1W + wix);
                }
                #pragma unroll
                for (int u = 0; u < 8; ++u) {
                    const float cv = scat[c0 + c + u];
                    af0 = fmaf(cv, vF[u].x, af0); af1 = fmaf(cv, vF[u].y, af1);
                    ag0 = fmaf(cv, vG[u].x, ag0); ag1 = fmaf(cv, vG[u].y, ag1);
                }
            }
            af0 += __shfl_xor_sync(0xffffffffu, af0, 1);
            af1 += __shfl_xor_sync(0xffffffffu, af1, 1);
            ag0 += __shfl_xor_sync(0xffffffffu, ag0, 1);
            ag1 += __shfl_xor_sync(0xffffffffu, ag1, 1);
        }
        if (!isA && ih == 0) {
            sFB[op][0] = af0; sFB[op][1] = af1; sFB[op][2] = ag0; sFB[op][3] = ag1;
        }
        __syncthreads();
        float hf0 = 0.f, hf1 = 0.f;
        if (isA) {
            af0 += sFB[op][0]; af1 += sFB[op][1];
            ag0 += sFB[op][2]; ag1 += sFB[op][3];
            hf0 = geluf(af0 + fubv.x);
            hf1 = geluf(af1 + fubv.y);
            const float hg0 = geluf(ag0 + wg1bv.x);
            const float hg1 = geluf(ag1 + wg1bv.y);
            float a0 = hf0 + hf1;
            float a1 = hf0 * hf0 + hf1 * hf1;
            float a2 = hg0 * wg2wv.x + hg1 * wg2wv.y;
            #pragma unroll
            for (int off = 2; off <= 16; off <<= 1) {
                a0 += __shfl_xor_sync(0xffffffffu, a0, off);
                a1 += __shfl_xor_sync(0xffffffffu, a1, off);
                a2 += __shfl_xor_sync(0xffffffffu, a2, off);
            }
            if (lane == 0) { sBR[wid][0] = a0; sBR[wid][1] = a1; sBR[wid][2] = a2; }
            barA();
            if (tid < 3) {
                const float s = sBR[0][tid] + sBR[1][tid] + sBR[2][tid] + sBR[3][tid];
                sF[tid] = s;
                st_peer_f32(peer_addr(smem_u32(&eF[tid]), peer), s);
            }
        }
        cluster_sync_();   // B3: fu-LN + wg2 partials exchanged

        // ================= PHASE 4 =================
        const float gw = sigmf(sF[2] + eF[2] + wg2b0) * sNov;
        if (tid < K_) sPers[tid] += sEvict[tid] * gw * 0.1f;

        float u0 = 0.f, u1 = 0.f;
        if (isA) {
            const float fsum = sF[0] + eF[0], fsq = sF[1] + eF[1];
            const float fmn = fsum * (1.f / D_);
            const float fvr = fsq * (1.f / D_) - fmn * fmn;
            const float frs = rsqrtf(fvr + EPSLN);
            const float outt0 = (hf0 - fmn) * frs * fulngv.x + fulnbv.x;
            const float outt1 = (hf1 - fmn) * frs * fulngv.y + fulnbv.y;
            u0 = outt0 + scat[og];
            u1 = outt1 + scat[og + 1];
            float b0 = u0 + u1;
            float b1 = u0 * u0 + u1 * u1;
            #pragma unroll
            for (int off = 2; off <= 16; off <<= 1) {
                b0 += __shfl_xor_sync(0xffffffffu, b0, off);
                b1 += __shfl_xor_sync(0xffffffffu, b1, off);
            }
            if (lane == 0) { sBR[wid][0] = b0; sBR[wid][1] = b1; }
            barA();
            if (tid < 2) {
                const float s = sBR[0][tid] + sBR[1][tid] + sBR[2][tid] + sBR[3][tid];
                sU[tid] = s;
                st_peer_f32(peer_addr(smem_u32(&eU[tid]), peer), s);
            }
        } else {
            // M update: one row per B thread (local + peer mirror)
            float nm[K_];
            #pragma unroll
            for (int j = 0; j < K_; ++j) {
                const float al = gw * sEvict[j];
                const float wr = (sG[gt][j] - sMean[j]) * sRstd[j] * cgB + cbB;
                nm[j] = sM[grow][j] * (1.f - al * sE[gt][j]) + al * wr;
            }
            float4* rowp = reinterpret_cast<float4*>(sM[grow]);
            rowp[0] = make_float4(nm[0],  nm[1],  nm[2],  nm[3]);
            rowp[1] = make_float4(nm[4],  nm[5],  nm[6],  nm[7]);
            rowp[2] = make_float4(nm[8],  nm[9],  nm[10], nm[11]);
            rowp[3] = make_float4(nm[12], nm[13], nm[14], nm[15]);
            uint32_t ra = peer_addr(smem_u32(&sM[grow][0]), peer);
            st_peer_f128(ra,      make_float4(nm[0],  nm[1],  nm[2],  nm[3]));
            st_peer_f128(ra + 16, make_float4(nm[4],  nm[5],  nm[6],  nm[7]));
            st_peer_f128(ra + 32, make_float4(nm[8],  nm[9],  nm[10], nm[11]));
            st_peer_f128(ra + 48, make_float4(nm[12], nm[13], nm[14], nm[15]));
        }
        cluster_sync_();   // B4: out-LN partials + peer M halves visible

        if (isA && ih == 0) {
            const float usum = sU[0] + eU[0], usq = sU[1] + eU[1];
            const float um = usum * (1.f / D_);
            const float uv = usq * (1.f / D_) - um * um;
            const float rr = rsqrtf(uv + EPSLN);
            float* po = out + ((size_t)t * B_ + b) * D_ + og;
            po[0] = (u0 - um) * rr * ongv.x + onbv.x;
            po[1] = (u1 - um) * rr * ongv.y + onbv.y;
        }
    }

    // proto = transpose(M, (1,0,2)) : [K, B, d]
    if (isA && ih == 0) {
        #pragma unroll
        for (int j = 0; j < K_; ++j) {
            out[(size_t)S_ * B_ * D_ + ((size_t)j * B_ + b) * D_ + og]     = sM[og][j];
            out[(size_t)S_ * B_ * D_ + ((size_t)j * B_ + b) * D_ + og + 1] = sM[og + 1][j];
        }
    }
}

extern "C" void kernel_launch(void* const* d_in, const int* in_sizes, int n_in,
                              void* d_out, int out_size) {
    (void)in_sizes; (void)n_in; (void)out_size;
    memunit_kernel<<<2 * B_, NT>>>(
        (const float*)d_in[0],  (const float*)d_in[1],
        (const float*)d_in[2],  (const float*)d_in[3],
        (const float*)d_in[4],  (const float*)d_in[5],
        (const float*)d_in[6],  (const float*)d_in[7],
        (const float*)d_in[8],  (const float*)d_in[9],
        (const float*)d_in[10], (const float*)d_in[11],
        (const float*)d_in[12], (const float*)d_in[13],
        (const float*)d_in[14], (const float*)d_in[15],
        (const float*)d_in[16], (const float*)d_in[17],
        (const float*)d_in[18], (const float*)d_in[19],
        (const float*)d_in[20], (const float*)d_in[21],
        (const float*)d_in[22], (const float*)d_in[23],
        (float*)d_out);
}